// round 5
// baseline (speedup 1.0000x reference)
#include <cuda_runtime.h>
#include <cstdint>

#define TT   512
#define BB   1024
#define H1   64
#define G1   256     // 4*H1
#define BT1  8
#define H2   32
#define G2   128     // 4*H2
#define BT2  4

typedef unsigned long long ull;

// h1 scratch, DUPLICATED values: g_h1d[(t*BB + b)*128 + dir*64 + ch] = (h,h)
__device__ ull g_h1d[(size_t)TT * BB * 128];

// ---- fast activations -----------------------------------------------------
__device__ __forceinline__ float tanh_(float x) {
    float y;
    asm("tanh.approx.f32 %0, %1;" : "=f"(y) : "f"(x));
    return y;
}
__device__ __forceinline__ float sigm(float x) {
    return fmaf(tanh_(x * 0.5f), 0.5f, 0.5f);
}

// ---- packed fp32x2 --------------------------------------------------------
__device__ __forceinline__ void ffma2(ull& acc, ull a, ull b) {
    asm("fma.rn.f32x2 %0, %1, %2, %0;" : "+l"(acc) : "l"(a), "l"(b));
}
__device__ __forceinline__ ull pack2(float lo, float hi) {
    ull r;
    asm("mov.b64 %0, {%1, %2};" : "=l"(r) : "f"(lo), "f"(hi));
    return r;
}
__device__ __forceinline__ float lo2(ull v) {
    float lo, hi;
    asm("mov.b64 {%0, %1}, %2;" : "=f"(lo), "=f"(hi) : "l"(v));
    return lo;
}
__device__ __forceinline__ void unpk(ull v, float& lo, float& hi) {
    asm("mov.b64 {%0, %1}, %2;" : "=f"(lo), "=f"(hi) : "l"(v));
}

// ---------------------------------------------------------------------------
// Kernel 1: bidirectional layer-1 LSTM.
// grid (128,2), block 256. thread = (gq = tid&63, ks = tid>>6).
// Thread owns gates 4gq..4gq+3 (2 packed pairs), k-slice [16ks,16ks+16).
// Warp = fixed ks -> h loads are broadcast LDS.64 of duplicated values.
// ---------------------------------------------------------------------------
__global__ __launch_bounds__(256, 2)
void lstm1_kernel(const float* __restrict__ x,
                  const float* __restrict__ wih_f, const float* __restrict__ whh_f,
                  const float* __restrict__ b_f,
                  const float* __restrict__ wih_r, const float* __restrict__ whh_r,
                  const float* __restrict__ b_r)
{
    const int dir = blockIdx.y;
    const int b0  = blockIdx.x * BT1;
    const int tid = threadIdx.x;
    const int gq  = tid & 63;
    const int ks  = tid >> 6;

    const float* wih = dir ? wih_r : wih_f;
    const float* whh = dir ? whh_r : whh_f;
    const float* bb  = dir ? b_r  : b_f;

    __shared__ float sxc[BT1][64];     // 2 KB: x chunk
    __shared__ ull   sh[BT1][H1];      // 4 KB: duplicated h
    __shared__ ull   sz[4][BT1][G1/2]; // 32 KB: gate-pair partials per k-slice

    for (int i = tid; i < BT1 * H1; i += 256) ((ull*)sh)[i] = 0ULL;

    // weights packed over gate pairs: wp[p][k] = (W[4gq+2p][16ks+k], W[4gq+2p+1][...])
    ull wp[2][16];
#pragma unroll
    for (int p = 0; p < 2; p++)
#pragma unroll
        for (int k = 0; k < 16; k++)
            wp[p][k] = pack2(whh[(4 * gq + 2 * p)     * H1 + 16 * ks + k],
                             whh[(4 * gq + 2 * p + 1) * H1 + 16 * ks + k]);

    float wi0 = wih[4 * gq], wi1 = wih[4 * gq + 1], wi2 = wih[4 * gq + 2], wi3 = wih[4 * gq + 3];
    float bs0 = bb[4 * gq],  bs1 = bb[4 * gq + 1],  bs2 = bb[4 * gq + 2],  bs3 = bb[4 * gq + 3];

    // cell pair per thread: (cbb, 2chp) and (cbb, 2chp+1)
    float c0 = 0.f, c1 = 0.f;
    const int cbb = tid >> 5;       // 0..7
    const int chp = tid & 31;

    __syncthreads();

    for (int tt = 0; tt < TT; ++tt) {
        const int t = dir ? (TT - 1 - tt) : tt;

        if ((tt & 63) == 0) {
            const int tbase = dir ? (448 - tt) : tt;
            for (int i = tid; i < BT1 * 64; i += 256) {
                int b = i >> 6, to = i & 63;
                sxc[b][to] = x[(size_t)(b0 + b) * TT + tbase + to];
            }
            __syncthreads();
        }
        const int ts = t & 63;

        ull acc0[BT1], acc1[BT1];
        if (ks == 0) {
#pragma unroll
            for (int b = 0; b < BT1; b++) {
                float xv = sxc[b][ts];
                acc0[b] = pack2(fmaf(xv, wi0, bs0), fmaf(xv, wi1, bs1));
                acc1[b] = pack2(fmaf(xv, wi2, bs2), fmaf(xv, wi3, bs3));
            }
        } else {
#pragma unroll
            for (int b = 0; b < BT1; b++) { acc0[b] = 0ULL; acc1[b] = 0ULL; }
        }
#pragma unroll
        for (int k = 0; k < 16; k++) {
#pragma unroll
            for (int b = 0; b < BT1; b++) {
                ull hv = sh[b][16 * ks + k];       // broadcast LDS.64 (dup value)
                ffma2(acc0[b], hv, wp[0][k]);
                ffma2(acc1[b], hv, wp[1][k]);
            }
        }
#pragma unroll
        for (int b = 0; b < BT1; b++) {
            ulonglong2 v; v.x = acc0[b]; v.y = acc1[b];
            *(ulonglong2*)&sz[ks][b][2 * gq] = v;   // pairs 2gq, 2gq+1
        }
        __syncthreads();

        // cell update: 2 adjacent cells per thread, packed reads
        {
            float zi0 = 0.f, zi1 = 0.f, zf0 = 0.f, zf1 = 0.f;
            float zg0 = 0.f, zg1 = 0.f, zo0 = 0.f, zo1 = 0.f;
#pragma unroll
            for (int s = 0; s < 4; s++) {
                float a, b2;
                unpk(sz[s][cbb][chp],      a, b2); zi0 += a; zi1 += b2;
                unpk(sz[s][cbb][32 + chp], a, b2); zf0 += a; zf1 += b2;
                unpk(sz[s][cbb][64 + chp], a, b2); zg0 += a; zg1 += b2;
                unpk(sz[s][cbb][96 + chp], a, b2); zo0 += a; zo1 += b2;
            }
            c0 = sigm(zf0) * c0 + sigm(zi0) * tanh_(zg0);
            float h0 = sigm(zo0) * tanh_(c0);
            c1 = sigm(zf1) * c1 + sigm(zi1) * tanh_(zg1);
            float h1v = sigm(zo1) * tanh_(c1);

            ulonglong2 hd; hd.x = pack2(h0, h0); hd.y = pack2(h1v, h1v);
            *(ulonglong2*)&sh[cbb][2 * chp] = hd;
            *(ulonglong2*)&g_h1d[((size_t)t * BB + (b0 + cbb)) * 128 + dir * 64 + 2 * chp] = hd;
        }
        __syncthreads();
    }
}

// ---------------------------------------------------------------------------
// Kernel 2: layer-2 forward scan + single reverse step + MLP head.
// grid 256, block 256. thread = (gq = tid&31, ks = tid>>5 in 0..7).
// Thread owns gates 4gq..4gq+3 (2 packed pairs); combined k-dim 160
// (128 input + 32 recurrent), slice [20ks, 20ks+20).
// buf row per batch = 160 dup-ull: [0,128) = h1 input, [128,160) = h2.
// ---------------------------------------------------------------------------
__global__ __launch_bounds__(256, 2)
void lstm2_kernel(const float* __restrict__ wih2f, const float* __restrict__ whh2f,
                  const float* __restrict__ b2f,
                  const float* __restrict__ wih2r, const float* __restrict__ b2r,
                  const float* __restrict__ w_fc1, const float* __restrict__ b_fc1,
                  const float* __restrict__ w_out, const float* __restrict__ b_out,
                  float* __restrict__ out)
{
    const int b0  = blockIdx.x * BT2;
    const int tid = threadIdx.x;
    const int gq  = tid & 31;
    const int ks  = tid >> 5;

    __shared__ ull   buf[2][BT2][160];   // 10 KB double buffer (dup values)
    __shared__ ull   sz2[8][BT2][G2/2];  // 16 KB partials
    __shared__ float slast[BT2][64];     // 1 KB
    __shared__ float sfc[BT2][64];       // 1 KB

    // combined weight row: k<128 -> wih2f, else whh2f
    ull wq[2][20];
#pragma unroll
    for (int p = 0; p < 2; p++) {
        const int g0 = 4 * gq + 2 * p, g1v = g0 + 1;
#pragma unroll
        for (int k = 0; k < 20; k++) {
            int kk = 20 * ks + k;
            float w0 = (kk < 128) ? wih2f[g0 * G2 + kk]  : whh2f[g0 * H2 + kk - 128];
            float w1 = (kk < 128) ? wih2f[g1v * G2 + kk] : whh2f[g1v * H2 + kk - 128];
            wq[p][k] = pack2(w0, w1);
        }
    }
    float bs0 = b2f[4 * gq], bs1 = b2f[4 * gq + 1], bs2 = b2f[4 * gq + 2], bs3 = b2f[4 * gq + 3];

    // zero h2 tails of both buffers
    if (tid < 128) {
        int b = tid >> 5, j = tid & 31;
        buf[0][b][128 + j] = 0ULL;
        buf[1][b][128 + j] = 0ULL;
    }
    // stage t=0 input tile
    {
        int b = tid >> 6, j = (tid & 63) * 2;
        ulonglong2 v = *(const ulonglong2*)&g_h1d[(size_t)(b0 + b) * 128 + j];
        *(ulonglong2*)&buf[0][b][j] = v;
    }

    float c = 0.f;
    const int cb  = tid >> 5;     // cell batch (tid<128)
    const int chh = tid & 31;

    __syncthreads();

    const float* szf = (const float*)sz2;   // [ks][b][128] float view

    for (int t = 0; t < TT; ++t) {
        const int cur = t & 1;

        ulonglong2 pre; pre.x = 0ULL; pre.y = 0ULL;
        const int pb = tid >> 6, pj = (tid & 63) * 2;
        if (t + 1 < TT)
            pre = *(const ulonglong2*)&g_h1d[((size_t)(t + 1) * BB + b0 + pb) * 128 + pj];

        ull acc0[BT2], acc1[BT2];
        if (ks == 0) {
#pragma unroll
            for (int b = 0; b < BT2; b++) {
                acc0[b] = pack2(bs0, bs1);
                acc1[b] = pack2(bs2, bs3);
            }
        } else {
#pragma unroll
            for (int b = 0; b < BT2; b++) { acc0[b] = 0ULL; acc1[b] = 0ULL; }
        }
#pragma unroll
        for (int k = 0; k < 20; k++) {
#pragma unroll
            for (int b = 0; b < BT2; b++) {
                ull hv = buf[cur][b][20 * ks + k];    // broadcast LDS.64
                ffma2(acc0[b], hv, wq[0][k]);
                ffma2(acc1[b], hv, wq[1][k]);
            }
        }
#pragma unroll
        for (int b = 0; b < BT2; b++) {
            ulonglong2 v; v.x = acc0[b]; v.y = acc1[b];
            *(ulonglong2*)&sz2[ks][b][2 * gq] = v;
        }
        __syncthreads();

        // cell update: 128 cells, threads 0..127
        if (tid < 128) {
            float zi = 0.f, zf = 0.f, zg = 0.f, zo = 0.f;
#pragma unroll
            for (int s = 0; s < 8; s++) {
                const float* r = szf + (s * BT2 + cb) * G2;
                zi += r[chh]; zf += r[32 + chh]; zg += r[64 + chh]; zo += r[96 + chh];
            }
            c = sigm(zf) * c + sigm(zi) * tanh_(zg);
            float h2 = sigm(zo) * tanh_(c);
            ull hd = pack2(h2, h2);
            buf[0][cb][128 + chh] = hd;
            buf[1][cb][128 + chh] = hd;
        }
        if (t + 1 < TT) *(ulonglong2*)&buf[1 - cur][pb][pj] = pre;
        __syncthreads();
    }
    // buf[1][b][0..128) = h1[T-1] (dup); buf[1][b][128..160) = final fwd h2 (dup)

    // layer-2 reverse: single step at t=T-1 from h=c=0
    {
        const int g2 = tid & 127;
        const int rb = (tid >> 7) * 2;      // batches rb, rb+1
        const float brv = b2r[g2];
        float a0 = brv, a1 = brv;
        const float* wr = wih2r + g2 * G2;
        for (int k = 0; k < G2; k++) {
            float wv = __ldg(wr + k);
            a0 = fmaf(lo2(buf[1][rb][k]),     wv, a0);
            a1 = fmaf(lo2(buf[1][rb + 1][k]), wv, a1);
        }
        float* zr = (float*)sz2;
        zr[rb * G2 + g2]       = a0;
        zr[(rb + 1) * G2 + g2] = a1;
    }
    __syncthreads();
    if (tid < 128) {
        const float* zr = (const float*)sz2;
        float zi = zr[cb * G2 + chh];
        float zg = zr[cb * G2 + 64 + chh], zo = zr[cb * G2 + 96 + chh];
        float cr = sigm(zi) * tanh_(zg);      // c_prev = 0
        float hr = sigm(zo) * tanh_(cr);
        slast[cb][chh]      = lo2(buf[1][cb][128 + chh]);
        slast[cb][32 + chh] = hr;
    }
    __syncthreads();

    // fc1 (64x64) + relu: 256 items
    {
        int b = tid >> 6, o = tid & 63;
        float a = b_fc1[o];
        const float* wf = w_fc1 + o * 64;
        for (int k = 0; k < 64; k++) a = fmaf(slast[b][k], __ldg(wf + k), a);
        sfc[b][o] = fmaxf(a, 0.f);
    }
    __syncthreads();

    if (tid < BT2) {
        float a = b_out[0];
        for (int k = 0; k < 64; k++) a = fmaf(sfc[tid][k], __ldg(w_out + k), a);
        out[b0 + tid] = sigm(a);
    }
}

// ---------------------------------------------------------------------------
extern "C" void kernel_launch(void* const* d_in, const int* in_sizes, int n_in,
                              void* d_out, int out_size)
{
    (void)in_sizes; (void)n_in; (void)out_size;
    const float* x     = (const float*)d_in[0];
    const float* wih1f = (const float*)d_in[1];
    const float* whh1f = (const float*)d_in[2];
    const float* b1f   = (const float*)d_in[3];
    const float* wih1r = (const float*)d_in[4];
    const float* whh1r = (const float*)d_in[5];
    const float* b1r   = (const float*)d_in[6];
    const float* wih2f = (const float*)d_in[7];
    const float* whh2f = (const float*)d_in[8];
    const float* b2f   = (const float*)d_in[9];
    const float* wih2r = (const float*)d_in[10];
    const float* b2r   = (const float*)d_in[12];
    const float* w_fc1 = (const float*)d_in[13];
    const float* b_fc1 = (const float*)d_in[14];
    const float* w_out = (const float*)d_in[15];
    const float* b_out = (const float*)d_in[16];
    float* out = (float*)d_out;

    lstm1_kernel<<<dim3(BB / BT1, 2), 256>>>(x, wih1f, whh1f, b1f, wih1r, whh1r, b1r);
    lstm2_kernel<<<BB / BT2, 256>>>(wih2f, whh2f, b2f, wih2r, b2r,
                                    w_fc1, b_fc1, w_out, b_out, out);
}

// round 6
// speedup vs baseline: 1.1271x; 1.1271x over previous
#include <cuda_runtime.h>
#include <cstdint>

#define TT   512
#define BB   1024
#define H1   64
#define G1   256     // 4*H1
#define BT1  8
#define H2   32
#define G2   128     // 4*H2
#define BT2  4

typedef unsigned long long ull;

// scratch: h1[t][b][j], j in [0,128): fwd half [0,64), rev half [64,128)
__device__ float g_h1[(size_t)TT * BB * 128];

// ---- fast activations -----------------------------------------------------
__device__ __forceinline__ float tanh_(float x) {
    float y;
    asm("tanh.approx.f32 %0, %1;" : "=f"(y) : "f"(x));
    return y;
}
__device__ __forceinline__ float sigm(float x) {
    return fmaf(tanh_(x * 0.5f), 0.5f, 0.5f);
}

// ---- packed fp32x2 fma ----------------------------------------------------
__device__ __forceinline__ void ffma2(ull& acc, ull a, ull b) {
    asm("fma.rn.f32x2 %0, %1, %2, %0;" : "+l"(acc) : "l"(a), "l"(b));
}
__device__ __forceinline__ ull pack2(float lo, float hi) {
    ull r;
    asm("mov.b64 %0, {%1, %2};" : "=l"(r) : "f"(lo), "f"(hi));
    return r;
}
__device__ __forceinline__ float hadd2(ull v) {
    float lo, hi;
    asm("mov.b64 {%0, %1}, %2;" : "=f"(lo), "=f"(hi) : "l"(v));
    return lo + hi;
}

// ---------------------------------------------------------------------------
// Kernel 1: bidirectional layer-1 LSTM, two-phase batch-split pipeline.
// grid = (128, 2), block = 256.  thread = (gp = tid&127, half = tid>>7).
// Thread owns gates {2gp, 2gp+1}, k-slice [32*half, 32*half+32).
// Batch halves: A = rows 0..3, B = rows 4..7.
// Step t: P1 = FMA(A,t) + cell(B,t-1);  P2 = FMA(B,t) + cell(A,t).
// ---------------------------------------------------------------------------
__global__ __launch_bounds__(256, 2)
void lstm1_kernel(const float* __restrict__ x,
                  const float* __restrict__ wih_f, const float* __restrict__ whh_f,
                  const float* __restrict__ b_f,
                  const float* __restrict__ wih_r, const float* __restrict__ whh_r,
                  const float* __restrict__ b_r)
{
    const int dir  = blockIdx.y;
    const int b0   = blockIdx.x * BT1;
    const int tid  = threadIdx.x;
    const int gp   = tid & 127;
    const int half = tid >> 7;

    const float* wih = dir ? wih_r : wih_f;
    const float* whh = dir ? whh_r : whh_f;
    const float* bb  = dir ? b_r  : b_f;

    __shared__ float sxc[BT1][64];      // 2 KB: x chunk (64 timesteps)
    __shared__ float sh[BT1][H1];       // 2 KB
    __shared__ float szA[BT1][G1];      // 8 KB
    __shared__ float szB[BT1][G1];      // 8 KB

    for (int i = tid; i < BT1 * H1; i += 256) ((float*)sh)[i] = 0.f;

    // weights: 2 gate rows x 32 k = 32 packed k-pairs (64 regs)
    ull wp0[16], wp1[16];
    {
        const ull* w0 = (const ull*)(whh + (2 * gp)     * H1 + 32 * half);
        const ull* w1 = (const ull*)(whh + (2 * gp + 1) * H1 + 32 * half);
#pragma unroll
        for (int j = 0; j < 16; j++) { wp0[j] = w0[j]; wp1[j] = w1[j]; }
    }
    const float wi0 = (half == 0) ? wih[2 * gp]     : 0.f;
    const float wi1 = (half == 0) ? wih[2 * gp + 1] : 0.f;
    const float bg0 = (half == 0) ? bb[2 * gp]      : 0.f;
    const float bg1 = (half == 0) ? bb[2 * gp + 1]  : 0.f;

    // cell states: c0 for (cb, ch) in half A, c1 for (cb+4, ch) in half B
    float c0 = 0.f, c1 = 0.f;
    const int cb = tid >> 6;            // 0..3
    const int ch = tid & 63;

    float* dst = half ? &szB[0][0] : &szA[0][0];

    __syncthreads();

    for (int tt = 0; tt < TT; ++tt) {
        const int t = dir ? (TT - 1 - tt) : tt;

        if ((tt & 63) == 0) {
            const int tbase = dir ? (448 - tt) : tt;
            for (int i = tid; i < BT1 * 64; i += 256) {
                int b = i >> 6, to = i & 63;
                sxc[b][to] = x[(size_t)(b0 + b) * TT + tbase + to];
            }
            __syncthreads();
        }
        const int ts = t & 63;

        // ================= P1: cell(B, t-1) + FMA(A, t) =================
        if (tt > 0) {
            const int tp  = dir ? (TT - tt) : (tt - 1);
            const int cb2 = cb + 4;
            float zi = szA[cb2][ch]       + szB[cb2][ch];
            float zf = szA[cb2][64 + ch]  + szB[cb2][64 + ch];
            float zg = szA[cb2][128 + ch] + szB[cb2][128 + ch];
            float zo = szA[cb2][192 + ch] + szB[cb2][192 + ch];
            c1 = sigm(zf) * c1 + sigm(zi) * tanh_(zg);
            float hv = sigm(zo) * tanh_(c1);
            sh[cb2][ch] = hv;
            g_h1[((size_t)tp * BB + (b0 + cb2)) * 128 + dir * 64 + ch] = hv;
        }
        {
            ull a0[4], a1[4];
            if (half == 0) {
#pragma unroll
                for (int b = 0; b < 4; b++) {
                    float xv = sxc[b][ts];
                    a0[b] = pack2(fmaf(xv, wi0, bg0), 0.f);
                    a1[b] = pack2(fmaf(xv, wi1, bg1), 0.f);
                }
            } else {
#pragma unroll
                for (int b = 0; b < 4; b++) { a0[b] = 0ULL; a1[b] = 0ULL; }
            }
#pragma unroll
            for (int j = 0; j < 8; j++) {
#pragma unroll
                for (int b = 0; b < 4; b++) {
                    ulonglong2 hv = *(const ulonglong2*)&sh[b][32 * half + 4 * j];
                    ffma2(a0[b], hv.x, wp0[2 * j]);
                    ffma2(a0[b], hv.y, wp0[2 * j + 1]);
                    ffma2(a1[b], hv.x, wp1[2 * j]);
                    ffma2(a1[b], hv.y, wp1[2 * j + 1]);
                }
            }
#pragma unroll
            for (int b = 0; b < 4; b++)
                *(ull*)(dst + b * G1 + 2 * gp) = pack2(hadd2(a0[b]), hadd2(a1[b]));
        }
        __syncthreads();

        // ================= P2: cell(A, t) + FMA(B, t) =================
        {
            float zi = szA[cb][ch]       + szB[cb][ch];
            float zf = szA[cb][64 + ch]  + szB[cb][64 + ch];
            float zg = szA[cb][128 + ch] + szB[cb][128 + ch];
            float zo = szA[cb][192 + ch] + szB[cb][192 + ch];
            c0 = sigm(zf) * c0 + sigm(zi) * tanh_(zg);
            float hv = sigm(zo) * tanh_(c0);
            sh[cb][ch] = hv;
            g_h1[((size_t)t * BB + (b0 + cb)) * 128 + dir * 64 + ch] = hv;
        }
        {
            ull a0[4], a1[4];
            if (half == 0) {
#pragma unroll
                for (int b = 0; b < 4; b++) {
                    float xv = sxc[b + 4][ts];
                    a0[b] = pack2(fmaf(xv, wi0, bg0), 0.f);
                    a1[b] = pack2(fmaf(xv, wi1, bg1), 0.f);
                }
            } else {
#pragma unroll
                for (int b = 0; b < 4; b++) { a0[b] = 0ULL; a1[b] = 0ULL; }
            }
#pragma unroll
            for (int j = 0; j < 8; j++) {
#pragma unroll
                for (int b = 0; b < 4; b++) {
                    ulonglong2 hv = *(const ulonglong2*)&sh[b + 4][32 * half + 4 * j];
                    ffma2(a0[b], hv.x, wp0[2 * j]);
                    ffma2(a0[b], hv.y, wp0[2 * j + 1]);
                    ffma2(a1[b], hv.x, wp1[2 * j]);
                    ffma2(a1[b], hv.y, wp1[2 * j + 1]);
                }
            }
#pragma unroll
            for (int b = 0; b < 4; b++)
                *(ull*)(dst + (b + 4) * G1 + 2 * gp) = pack2(hadd2(a0[b]), hadd2(a1[b]));
        }
        __syncthreads();
    }

    // epilogue: cell(B, t_last)
    {
        const int tp  = dir ? 0 : (TT - 1);
        const int cb2 = cb + 4;
        float zi = szA[cb2][ch]       + szB[cb2][ch];
        float zf = szA[cb2][64 + ch]  + szB[cb2][64 + ch];
        float zg = szA[cb2][128 + ch] + szB[cb2][128 + ch];
        float zo = szA[cb2][192 + ch] + szB[cb2][192 + ch];
        c1 = sigm(zf) * c1 + sigm(zi) * tanh_(zg);
        float hv = sigm(zo) * tanh_(c1);
        g_h1[((size_t)tp * BB + (b0 + cb2)) * 128 + dir * 64 + ch] = hv;
    }
}

// ---------------------------------------------------------------------------
// Kernel 2: layer-2 forward scan + single reverse step + MLP head,
// two-phase batch-split pipeline.
// grid = 256, block = 256.  thread = (gp = tid&63, q = tid>>6 in 0..3).
// Thread owns gates {2gp, 2gp+1}; k-dim (160 = 128 inp + 32 rec) split 40/q.
// Batch halves: A = rows {0,1}, B = rows {2,3}.
// ---------------------------------------------------------------------------
__global__ __launch_bounds__(256, 2)
void lstm2_kernel(const float* __restrict__ wih2f, const float* __restrict__ whh2f,
                  const float* __restrict__ b2f,
                  const float* __restrict__ wih2r, const float* __restrict__ b2r,
                  const float* __restrict__ w_fc1, const float* __restrict__ b_fc1,
                  const float* __restrict__ w_out, const float* __restrict__ b_out,
                  float* __restrict__ out)
{
    const int b0  = blockIdx.x * BT2;
    const int tid = threadIdx.x;
    const int gp  = tid & 63;
    const int q   = tid >> 6;

    __shared__ float sin_[2][BT2][G2];  // 4 KB double buffer
    __shared__ float sh2[BT2][H2];      // 512 B
    __shared__ float sz2[4][BT2][G2];   // 8 KB partials
    __shared__ float slast[BT2][64];    // 1 KB
    __shared__ float sfc[BT2][64];      // 1 KB

    // weights: 2 gates x 40 k = 40 packed k-pairs (80 regs)
    ull wq0[20], wq1[20];
    {
        const int g0 = 2 * gp, g1v = 2 * gp + 1;
        if (q < 3) {
            const ull* w0 = (const ull*)(wih2f + g0 * G2 + 40 * q);
            const ull* w1 = (const ull*)(wih2f + g1v * G2 + 40 * q);
#pragma unroll
            for (int j = 0; j < 20; j++) { wq0[j] = w0[j]; wq1[j] = w1[j]; }
        } else {
            const ull* w0 = (const ull*)(wih2f + g0 * G2 + 120);
            const ull* w1 = (const ull*)(wih2f + g1v * G2 + 120);
#pragma unroll
            for (int j = 0; j < 4; j++) { wq0[j] = w0[j]; wq1[j] = w1[j]; }
            const ull* h0 = (const ull*)(whh2f + g0 * H2);
            const ull* h1 = (const ull*)(whh2f + g1v * H2);
#pragma unroll
            for (int j = 0; j < 16; j++) { wq0[4 + j] = h0[j]; wq1[4 + j] = h1[j]; }
        }
    }
    const float bg0 = (q == 0) ? b2f[2 * gp]     : 0.f;
    const float bg1 = (q == 0) ? b2f[2 * gp + 1] : 0.f;

    for (int i = tid; i < BT2 * H2; i += 256) ((float*)sh2)[i] = 0.f;

    // stage h1[t=0] tile (512 contiguous floats), float2 per thread
    {
        const float2* src = (const float2*)(g_h1 + (size_t)b0 * 128);
        ((float2*)sin_[0])[tid] = src[tid];
    }

    // cell states: tid<64 active. c0: batch tid>>5 (A), c1: batch 2+(tid>>5) (B)
    float c0 = 0.f, c1 = 0.f;
    const int cbl = tid >> 5;           // 0..1 when tid<64
    const int chh = tid & 31;

    __syncthreads();

    const float* szf = (const float*)sz2;   // [s][b][128] float view
    const int pb = tid >> 6, pj = (tid & 63) * 2;

    for (int t = 0; t < TT; ++t) {
        const int cur = t & 1;

        float2 pre = make_float2(0.f, 0.f);
        if (t + 1 < TT)
            pre = *(const float2*)(g_h1 + ((size_t)(t + 1) * BB + b0 + pb) * 128 + pj);

        // ================= P1: cell(B, t-1) + FMA(A, t) =================
        if (t > 0 && tid < 64) {
            const int cb2 = 2 + cbl;
            float zi = 0.f, zf = 0.f, zg = 0.f, zo = 0.f;
#pragma unroll
            for (int s = 0; s < 4; s++) {
                const float* r = szf + (s * BT2 + cb2) * G2;
                zi += r[chh]; zf += r[32 + chh]; zg += r[64 + chh]; zo += r[96 + chh];
            }
            c1 = sigm(zf) * c1 + sigm(zi) * tanh_(zg);
            sh2[cb2][chh] = sigm(zo) * tanh_(c1);
        }
        {
            ull a0[2], a1[2];
#pragma unroll
            for (int b = 0; b < 2; b++) {
                a0[b] = pack2(bg0, 0.f);
                a1[b] = pack2(bg1, 0.f);
            }
            if (q < 3) {
#pragma unroll
                for (int j = 0; j < 10; j++) {
#pragma unroll
                    for (int b = 0; b < 2; b++) {
                        ulonglong2 v = *(const ulonglong2*)&sin_[cur][b][40 * q + 4 * j];
                        ffma2(a0[b], v.x, wq0[2 * j]);
                        ffma2(a0[b], v.y, wq0[2 * j + 1]);
                        ffma2(a1[b], v.x, wq1[2 * j]);
                        ffma2(a1[b], v.y, wq1[2 * j + 1]);
                    }
                }
            } else {
#pragma unroll
                for (int j = 0; j < 2; j++) {
#pragma unroll
                    for (int b = 0; b < 2; b++) {
                        ulonglong2 v = *(const ulonglong2*)&sin_[cur][b][120 + 4 * j];
                        ffma2(a0[b], v.x, wq0[2 * j]);
                        ffma2(a0[b], v.y, wq0[2 * j + 1]);
                        ffma2(a1[b], v.x, wq1[2 * j]);
                        ffma2(a1[b], v.y, wq1[2 * j + 1]);
                    }
                }
#pragma unroll
                for (int j = 0; j < 8; j++) {
#pragma unroll
                    for (int b = 0; b < 2; b++) {
                        ulonglong2 v = *(const ulonglong2*)&sh2[b][4 * j];
                        ffma2(a0[b], v.x, wq0[4 + 2 * j]);
                        ffma2(a0[b], v.y, wq0[4 + 2 * j + 1]);
                        ffma2(a1[b], v.x, wq1[4 + 2 * j]);
                        ffma2(a1[b], v.y, wq1[4 + 2 * j + 1]);
                    }
                }
            }
#pragma unroll
            for (int b = 0; b < 2; b++)
                *(ull*)&sz2[q][b][2 * gp] = pack2(hadd2(a0[b]), hadd2(a1[b]));
        }
        if (t + 1 < TT) *(float2*)&sin_[1 - cur][pb][pj] = pre;
        __syncthreads();

        // ================= P2: cell(A, t) + FMA(B, t) =================
        if (tid < 64) {
            float zi = 0.f, zf = 0.f, zg = 0.f, zo = 0.f;
#pragma unroll
            for (int s = 0; s < 4; s++) {
                const float* r = szf + (s * BT2 + cbl) * G2;
                zi += r[chh]; zf += r[32 + chh]; zg += r[64 + chh]; zo += r[96 + chh];
            }
            c0 = sigm(zf) * c0 + sigm(zi) * tanh_(zg);
            sh2[cbl][chh] = sigm(zo) * tanh_(c0);
        }
        {
            ull a0[2], a1[2];
#pragma unroll
            for (int b = 0; b < 2; b++) {
                a0[b] = pack2(bg0, 0.f);
                a1[b] = pack2(bg1, 0.f);
            }
            if (q < 3) {
#pragma unroll
                for (int j = 0; j < 10; j++) {
#pragma unroll
                    for (int b = 0; b < 2; b++) {
                        ulonglong2 v = *(const ulonglong2*)&sin_[cur][b + 2][40 * q + 4 * j];
                        ffma2(a0[b], v.x, wq0[2 * j]);
                        ffma2(a0[b], v.y, wq0[2 * j + 1]);
                        ffma2(a1[b], v.x, wq1[2 * j]);
                        ffma2(a1[b], v.y, wq1[2 * j + 1]);
                    }
                }
            } else {
#pragma unroll
                for (int j = 0; j < 2; j++) {
#pragma unroll
                    for (int b = 0; b < 2; b++) {
                        ulonglong2 v = *(const ulonglong2*)&sin_[cur][b + 2][120 + 4 * j];
                        ffma2(a0[b], v.x, wq0[2 * j]);
                        ffma2(a0[b], v.y, wq0[2 * j + 1]);
                        ffma2(a1[b], v.x, wq1[2 * j]);
                        ffma2(a1[b], v.y, wq1[2 * j + 1]);
                    }
                }
#pragma unroll
                for (int j = 0; j < 8; j++) {
#pragma unroll
                    for (int b = 0; b < 2; b++) {
                        ulonglong2 v = *(const ulonglong2*)&sh2[b + 2][4 * j];
                        ffma2(a0[b], v.x, wq0[4 + 2 * j]);
                        ffma2(a0[b], v.y, wq0[4 + 2 * j + 1]);
                        ffma2(a1[b], v.x, wq1[4 + 2 * j]);
                        ffma2(a1[b], v.y, wq1[4 + 2 * j + 1]);
                    }
                }
            }
#pragma unroll
            for (int b = 0; b < 2; b++)
                *(ull*)&sz2[q][b + 2][2 * gp] = pack2(hadd2(a0[b]), hadd2(a1[b]));
        }
        __syncthreads();
    }

    // epilogue: cell(B, TT-1)
    if (tid < 64) {
        const int cb2 = 2 + cbl;
        float zi = 0.f, zf = 0.f, zg = 0.f, zo = 0.f;
#pragma unroll
        for (int s = 0; s < 4; s++) {
            const float* r = szf + (s * BT2 + cb2) * G2;
            zi += r[chh]; zf += r[32 + chh]; zg += r[64 + chh]; zo += r[96 + chh];
        }
        c1 = sigm(zf) * c1 + sigm(zi) * tanh_(zg);
        sh2[cb2][chh] = sigm(zo) * tanh_(c1);
    }
    __syncthreads();
    // sh2 = final forward h2 (all 4 batches); sin_[1] = h1[T-1] tile.

    // layer-2 reverse: single step at t = T-1 from h=c=0.
    // thread = (g2 = tid&127, rb = tid>>7): batches 2*rb, 2*rb+1
    {
        const int g2 = tid & 127;
        const int rb = tid >> 7;
        const float brv = b2r[g2];
        float a0 = brv, a1 = brv;
        const float* wr = wih2r + g2 * G2;
        for (int k = 0; k < G2; k++) {
            float wv = __ldg(wr + k);
            a0 = fmaf(sin_[1][2 * rb][k],     wv, a0);
            a1 = fmaf(sin_[1][2 * rb + 1][k], wv, a1);
        }
        float* zr = (float*)sz2;
        zr[2 * rb * G2 + g2]       = a0;
        zr[(2 * rb + 1) * G2 + g2] = a1;
    }
    __syncthreads();
    if (tid < 128) {
        const int cb4 = tid >> 5;       // 0..3
        const float* zr = (const float*)sz2;
        float zi = zr[cb4 * G2 + chh];
        float zg = zr[cb4 * G2 + 64 + chh], zo = zr[cb4 * G2 + 96 + chh];
        float cr = sigm(zi) * tanh_(zg);      // c_prev = 0
        float hr = sigm(zo) * tanh_(cr);
        slast[cb4][chh]      = sh2[cb4][chh];
        slast[cb4][32 + chh] = hr;
    }
    __syncthreads();

    // fc1 (64x64) + relu: 256 items
    {
        int b = tid >> 6, o = tid & 63;
        float a = b_fc1[o];
        const float* wf = w_fc1 + o * 64;
        for (int k = 0; k < 64; k++) a = fmaf(slast[b][k], __ldg(wf + k), a);
        sfc[b][o] = fmaxf(a, 0.f);
    }
    __syncthreads();

    if (tid < BT2) {
        float a = b_out[0];
        for (int k = 0; k < 64; k++) a = fmaf(sfc[tid][k], __ldg(w_out + k), a);
        out[b0 + tid] = sigm(a);
    }
}

// ---------------------------------------------------------------------------
extern "C" void kernel_launch(void* const* d_in, const int* in_sizes, int n_in,
                              void* d_out, int out_size)
{
    (void)in_sizes; (void)n_in; (void)out_size;
    const float* x     = (const float*)d_in[0];
    const float* wih1f = (const float*)d_in[1];
    const float* whh1f = (const float*)d_in[2];
    const float* b1f   = (const float*)d_in[3];
    const float* wih1r = (const float*)d_in[4];
    const float* whh1r = (const float*)d_in[5];
    const float* b1r   = (const float*)d_in[6];
    const float* wih2f = (const float*)d_in[7];
    const float* whh2f = (const float*)d_in[8];
    const float* b2f   = (const float*)d_in[9];
    const float* wih2r = (const float*)d_in[10];
    const float* b2r   = (const float*)d_in[12];
    const float* w_fc1 = (const float*)d_in[13];
    const float* b_fc1 = (const float*)d_in[14];
    const float* w_out = (const float*)d_in[15];
    const float* b_out = (const float*)d_in[16];
    float* out = (float*)d_out;

    lstm1_kernel<<<dim3(BB / BT1, 2), 256>>>(x, wih1f, whh1f, b1f, wih1r, whh1r, b1r);
    lstm2_kernel<<<BB / BT2, 256>>>(wih2f, whh2f, b2f, wih2r, b2r,
                                    w_fc1, b_fc1, w_out, b_out, out);
}